// round 7
// baseline (speedup 1.0000x reference)
#include <cuda_runtime.h>
#include <cstdint>

// ---------------------------------------------------------------------------
// NodePredictor: y[b,n,:] = x[b,n,:] @ W[n] + b[n], out = y reshaped [B, N*DOUT]
// B=2048, N=64, DIN=DOUT=512, fp32. sm_100 legacy path (tcgen05 ungated only
// on sm_100a, not available under this harness's compile target).
//
// R7: smem-BW attack. CTA tile 128M x 256N, 8 warps, warptile 64x64
// (MMA:LDSM = 4:1, -31% smem bytes/FLOP vs R6's 128x128/64x32).
// A rounded to tf32 during staging; B pre-rounded in g_Wt prepass.
// ---------------------------------------------------------------------------

static constexpr int B_DIM   = 2048;
static constexpr int N_NODES = 64;
static constexpr int DIN     = 512;
static constexpr int DOUT    = 512;
static constexpr int OUT_W   = N_NODES * DOUT;   // 32768

static constexpr int TILE_M  = 128;
static constexpr int TILE_N  = 256;
static constexpr int TILE_K  = 32;               // 32 tf32 = 128 B row
static constexpr int K_ITERS = DIN / TILE_K;     // 16
static constexpr int THREADS = 256;
static constexpr int STAGES  = 3;

static constexpr int A_BYTES = TILE_M * 128;     // 16 KB
static constexpr int B_BYTES = TILE_N * 128;     // 32 KB
static constexpr int STAGE_BYTES = A_BYTES + B_BYTES;             // 48 KB
static constexpr int SMEM_BIAS   = STAGES * STAGE_BYTES;          // 147456
static constexpr int SMEM_TOTAL  = SMEM_BIAS + TILE_N * 4;        // +1024

// 64 MB scratch: Wt[n][dout][din], tf32(RNA)-rounded fp32 bits
__device__ float g_Wt[(size_t)N_NODES * DOUT * DIN];

// ---------------------------------------------------------------------------
__device__ __forceinline__ uint32_t smem_u32(const void* p) {
    uint32_t a;
    asm("{ .reg .u64 t; cvta.to.shared.u64 t, %1; cvt.u32.u64 %0, t; }" : "=r"(a) : "l"(p));
    return a;
}
__device__ __forceinline__ uint32_t rna_tf32(float x) {
    uint32_t r;
    asm("cvt.rna.tf32.f32 %0, %1;" : "=r"(r) : "f"(x));
    return r;
}
__device__ __forceinline__ uint32_t sw128(uint32_t off) {
    return off ^ ((off >> 3) & 0x70u);
}
__device__ __forceinline__ void cp_async16(uint32_t smem_dst, const void* gmem_src) {
    asm volatile("cp.async.cg.shared.global [%0], [%1], 16;"
                 :: "r"(smem_dst), "l"(gmem_src) : "memory");
}
__device__ __forceinline__ void cp_commit() {
    asm volatile("cp.async.commit_group;" ::: "memory");
}
template <int N>
__device__ __forceinline__ void cp_wait() {
    asm volatile("cp.async.wait_group %0;" :: "n"(N) : "memory");
}
__device__ __forceinline__ void ldsm_x4(uint32_t* r, uint32_t addr) {
    asm volatile("ldmatrix.sync.aligned.m8n8.x4.shared.b16 {%0,%1,%2,%3}, [%4];"
                 : "=r"(r[0]), "=r"(r[1]), "=r"(r[2]), "=r"(r[3]) : "r"(addr));
}
__device__ __forceinline__ void mma_tf32(float* c, const uint32_t* a, uint32_t b0, uint32_t b1) {
    asm volatile(
        "mma.sync.aligned.m16n8k8.row.col.f32.tf32.tf32.f32 "
        "{%0,%1,%2,%3}, {%4,%5,%6,%7}, {%8,%9}, {%0,%1,%2,%3};"
        : "+f"(c[0]), "+f"(c[1]), "+f"(c[2]), "+f"(c[3])
        : "r"(a[0]), "r"(a[1]), "r"(a[2]), "r"(a[3]), "r"(b0), "r"(b1));
}
__device__ __forceinline__ void sts128(uint32_t addr, uint32_t r0, uint32_t r1,
                                       uint32_t r2, uint32_t r3) {
    asm volatile("st.shared.v4.b32 [%0], {%1, %2, %3, %4};"
                 :: "r"(addr), "r"(r0), "r"(r1), "r"(r2), "r"(r3) : "memory");
}

// ---------------------------------------------------------------------------
// Pre-pass: Wt[n][o][i] = rna_tf32(W[n][i][o])
// ---------------------------------------------------------------------------
__global__ void wt_transpose_kernel(const float* __restrict__ W) {
    __shared__ float tile[32][33];
    const int n  = blockIdx.z;
    const int i0 = blockIdx.x * 32;
    const int o0 = blockIdx.y * 32;
    const int tx = threadIdx.x, ty = threadIdx.y;   // 32 x 8

    const float* src = W + ((size_t)n * DIN + i0) * DOUT + o0;
#pragma unroll
    for (int r = 0; r < 32; r += 8)
        tile[ty + r][tx] = src[(size_t)(ty + r) * DOUT + tx];
    __syncthreads();

    float* dst = g_Wt + ((size_t)n * DOUT + o0) * DIN + i0;
#pragma unroll
    for (int r = 0; r < 32; r += 8)
        dst[(size_t)(ty + r) * DIN + tx] = __uint_as_float(rna_tf32(tile[tx][ty + r]));
}

// ---------------------------------------------------------------------------
// Main GEMM: CTA = [128M x 256N] tile of one node. 8 warps 2x4, warptile 64x64.
// ---------------------------------------------------------------------------
__global__ __launch_bounds__(THREADS, 1)
void node_gemm_kernel(const float* __restrict__ x, const float* __restrict__ bias,
                      float* __restrict__ out) {
    extern __shared__ char smem[];
    const uint32_t sbase = smem_u32(smem);
    const int tid  = threadIdx.x;
    const int wid  = tid >> 5;
    const int lane = tid & 31;

    // block decode: nt fastest (L2 reuse of A slab), then mt, then node
    const int bx = blockIdx.x;
    const int n  = bx >> 5;
    const int mt = (bx >> 1) & 15;
    const int nt = bx & 1;
    const int m_base = mt * TILE_M;
    const int o_base = nt * TILE_N;

    reinterpret_cast<float*>(smem + SMEM_BIAS)[tid] = bias[n * DOUT + o_base + tid];

    // ---- staging
    // A (128 rows): thread t -> row t/2, 16B-chunks (t&1)*4..+3  (LDG+cvt+STS)
    // B (256 rows): thread t -> row t, 8x16B cp.async
    const int a_st_row = tid >> 1;
    const int a_st_cb  = (tid & 1) * 4;
    const float* a_src = x + ((size_t)(m_base + a_st_row) * N_NODES + n) * DIN + a_st_cb * 4;
    const float* b_src = g_Wt + ((size_t)(n * DOUT + o_base + tid)) * DIN;
    uint32_t a_dst[4], b_dst[8];
#pragma unroll
    for (int j = 0; j < 4; ++j)
        a_dst[j] = sw128((uint32_t)a_st_row * 128u + (uint32_t)(a_st_cb + j) * 16u);
#pragma unroll
    for (int j = 0; j < 8; ++j)
        b_dst[j] = sw128((uint32_t)tid * 128u + (uint32_t)j * 16u);

    auto issue_b = [&](int stage, int kc) {
        const uint32_t bs = sbase + stage * STAGE_BYTES + A_BYTES;
        const float* bp = b_src + kc * TILE_K;
#pragma unroll
        for (int j = 0; j < 8; ++j) cp_async16(bs + b_dst[j], bp + j * 4);
        cp_commit();
    };
    auto ldg_a = [&](float4* v, int kc) {
        const float4* ap = reinterpret_cast<const float4*>(a_src + kc * TILE_K);
#pragma unroll
        for (int j = 0; j < 4; ++j) v[j] = ap[j];
    };
    auto sts_a = [&](int stage, const float4* v) {
        const uint32_t as = sbase + stage * STAGE_BYTES;
#pragma unroll
        for (int j = 0; j < 4; ++j)
            sts128(as + a_dst[j], rna_tf32(v[j].x), rna_tf32(v[j].y),
                   rna_tf32(v[j].z), rna_tf32(v[j].w));
    };

    // ---- ldmatrix lane address components
    const int wm = wid >> 2;       // 0..1  (M): 64 rows
    const int wn = wid & 3;        // 0..3  (N): 64 cols
    const uint32_t a_row  = (uint32_t)(wm * 64 + (lane & 15));
    const uint32_t a_cadd = (uint32_t)(lane >> 4);
    const uint32_t b_row  = (uint32_t)(wn * 64 + ((lane >> 4) << 3) + (lane & 7));
    const uint32_t b_cadd = (uint32_t)((lane >> 3) & 1);

    float c[4][8][4];
#pragma unroll
    for (int i = 0; i < 4; ++i)
#pragma unroll
        for (int j = 0; j < 8; ++j)
#pragma unroll
            for (int k = 0; k < 4; ++k) c[i][j][k] = 0.0f;

    // pure ldsm+mma consumer: per ks 8 ldsm.x4 feed 32 MMAs
    auto compute = [&](int stage) {
        const uint32_t as = sbase + stage * STAGE_BYTES;
        const uint32_t bs = as + A_BYTES;
#pragma unroll
        for (int ks = 0; ks < 4; ++ks) {
            const uint32_t ac = 2 * ks + a_cadd;
            const uint32_t bc = 2 * ks + b_cadd;
            uint32_t a[4][4];
#pragma unroll
            for (int m = 0; m < 4; ++m)
                ldsm_x4(a[m], as + sw128((a_row + m * 16) * 128u + ac * 16u));
            uint32_t bq[16];
#pragma unroll
            for (int g = 0; g < 4; ++g)
                ldsm_x4(bq + 4 * g, bs + sw128((b_row + g * 16) * 128u + bc * 16u));
#pragma unroll
            for (int m = 0; m < 4; ++m)
#pragma unroll
                for (int q = 0; q < 8; ++q)
                    mma_tf32(c[m][q], a[m], bq[2 * q], bq[2 * q + 1]);
        }
    };

    // ---- prologue: fill stages 0 and 1
    {
        float4 v0[4], v1[4];
        ldg_a(v0, 0);
        ldg_a(v1, 1);
        issue_b(0, 0);
        issue_b(1, 1);
        sts_a(0, v0);
        sts_a(1, v1);
        cp_wait<0>();
        __syncthreads();
    }

    int s = 0;
    for (int kc = 0; kc < K_ITERS; ++kc) {
        const int s_issue = (s + 2 >= STAGES) ? s + 2 - STAGES : s + 2;

        float4 vpre[4];
        const bool pre = (kc + 2 < K_ITERS);
        if (pre) {
            issue_b(s_issue, kc + 2);   // async B for stage kc+2
            ldg_a(vpre, kc + 2);        // LDG A held in regs across compute
        }

        compute(s);

        if (pre) sts_a(s_issue, vpre);  // round + store A for stage kc+2

        if (kc + 1 < K_ITERS) {
            if (kc + 1 == K_ITERS - 1) cp_wait<0>(); else cp_wait<1>();
            __syncthreads();
        }
        s = (s + 1 == STAGES) ? 0 : s + 1;
    }

    // ---- epilogue: add bias, store (c0,c1)/(c2,c3) as float2
    const float* bsm = reinterpret_cast<const float*>(smem + SMEM_BIAS);
    const int r_top = m_base + wm * 64 + (lane >> 2);
    const int lc0   = wn * 64 + (lane & 3) * 2;
#pragma unroll
    for (int m = 0; m < 4; ++m) {
#pragma unroll
        for (int q = 0; q < 8; ++q) {
            const int lc = lc0 + q * 8;
            const float b0 = bsm[lc], b1 = bsm[lc + 1];
            float* d0 = out + (size_t)(r_top + m * 16) * OUT_W + n * DOUT + o_base + lc;
            float* d1 = d0 + 8 * OUT_W;
            float2 v0 = { c[m][q][0] + b0, c[m][q][1] + b1 };
            float2 v1 = { c[m][q][2] + b0, c[m][q][3] + b1 };
            *reinterpret_cast<float2*>(d0) = v0;
            *reinterpret_cast<float2*>(d1) = v1;
        }
    }
}

// ---------------------------------------------------------------------------
extern "C" void kernel_launch(void* const* d_in, const int* in_sizes, int n_in,
                              void* d_out, int out_size) {
    const float* x = (const float*)d_in[0];
    const float* W = (const float*)d_in[1];
    const float* b = (const float*)d_in[2];
    float* out = (float*)d_out;

    cudaFuncSetAttribute(node_gemm_kernel,
                         cudaFuncAttributeMaxDynamicSharedMemorySize, SMEM_TOTAL);

    wt_transpose_kernel<<<dim3(DIN / 32, DOUT / 32, N_NODES), dim3(32, 8)>>>(W);

    const int grid = N_NODES * (B_DIM / TILE_M) * (DOUT / TILE_N);  // 64*16*2 = 2048
    node_gemm_kernel<<<grid, THREADS, SMEM_TOTAL>>>(x, b, out);
}